// round 1
// baseline (speedup 1.0000x reference)
#include <cuda_runtime.h>
#include <stdint.h>

#define N_ANCH   25200
#define NDIM     85
#define NCLS     80
#define TOPK     1000
#define NTHREADS 1024
#define NPT      25      // ceil(25200/1024)
#define CAND     2048

__global__ __launch_bounds__(NTHREADS)
void yolo_topk_post_kernel(const float* __restrict__ pred,
                           float* __restrict__ scores_out,
                           float* __restrict__ boxes_out)
{
    __shared__ unsigned int       hist[256];
    __shared__ unsigned long long keys[CAND];
    __shared__ int                s_cnt;
    __shared__ unsigned int       s_sel;
    __shared__ unsigned int       s_k;

    const int tid  = threadIdx.x;
    const int lane = tid & 31;
    const int b    = blockIdx.x;
    const float* batch = pred + (size_t)b * N_ANCH * NDIM;

    // ---- Phase 1: load score bits into registers ----
    // fp32 scores are in [0,1): positive floats, so uint bit order == value order.
    unsigned int v[NPT];
#pragma unroll
    for (int s = 0; s < NPT; s++) {
        int i = s * NTHREADS + tid;
        v[s] = (i < N_ANCH) ? __float_as_uint(batch[(size_t)i * NDIM + 4]) : 0u;
    }

    if (tid == 0) s_k = TOPK;
    __syncthreads();

    // ---- Phase 2: 4-pass radix select for the TOPK-th largest bit pattern ----
    unsigned int prefix = 0, prefmask = 0;
    for (int pass = 0; pass < 4; pass++) {
        const int shift = 24 - 8 * pass;
        if (tid < 256) hist[tid] = 0;
        __syncthreads();

        // warp-aggregated histogram of the current byte among prefix-matching items
#pragma unroll
        for (int s = 0; s < NPT; s++) {
            int i = s * NTHREADS + tid;
            unsigned int bits = v[s];
            bool ok = (i < N_ANCH) && ((bits & prefmask) == prefix);
            unsigned int digit = ok ? ((bits >> shift) & 255u) : 0xffffffffu;
            unsigned int m = __match_any_sync(0xffffffffu, digit);
            int leader = __ffs(m) - 1;
            if (ok && lane == leader)
                atomicAdd(&hist[digit], (unsigned int)__popc(m));
        }
        __syncthreads();

        unsigned int kcur = s_k;   // snapshot before anyone updates it
        __syncthreads();

        // in-place suffix scan: hist[d] := count(digit >= d)
        for (int off = 1; off < 256; off <<= 1) {
            unsigned int t = 0;
            if (tid < 256 && tid + off < 256) t = hist[tid + off];
            __syncthreads();
            if (tid < 256) hist[tid] += t;
            __syncthreads();
        }

        if (tid < 256) {
            unsigned int ge = hist[tid];
            unsigned int gt = (tid == 255) ? 0u : hist[tid + 1];
            if (ge >= kcur && gt < kcur) {      // exactly one digit satisfies this
                s_sel = (unsigned int)tid;
                s_k   = kcur - gt;              // rank within the tied digit
            }
        }
        __syncthreads();
        prefix   |= s_sel << shift;
        prefmask |= 255u << shift;
        __syncthreads();
    }
    const unsigned int T = prefix;   // bit pattern of the 1000th-largest score

    // ---- Phase 3: compact all candidates with bits >= T ----
    if (tid == 0) s_cnt = 0;
    __syncthreads();
#pragma unroll
    for (int s = 0; s < NPT; s++) {
        int i = s * NTHREADS + tid;
        if (i < N_ANCH && v[s] >= T) {
            int p = atomicAdd(&s_cnt, 1);
            if (p < CAND) {
                // key: value-desc primary, index-asc secondary (~i is larger for smaller i)
                keys[p] = ((unsigned long long)v[s] << 32) |
                          (unsigned int)(~(unsigned int)i);
            }
        }
    }
    __syncthreads();
    int cnt = s_cnt; if (cnt > CAND) cnt = CAND;
    for (int i = tid; i < CAND; i += NTHREADS)
        if (i >= cnt) keys[i] = 0ull;           // padding sorts last
    __syncthreads();

    // ---- Phase 4: bitonic sort, descending (reproduces jax.lax.top_k order) ----
    for (int ksz = 2; ksz <= CAND; ksz <<= 1) {
        for (int j = ksz >> 1; j > 0; j >>= 1) {
            for (int t = tid; t < CAND; t += NTHREADS) {
                int l = t ^ j;
                if (l > t) {
                    unsigned long long a = keys[t], c = keys[l];
                    bool sw = ((t & ksz) == 0) ? (a < c) : (a > c);
                    if (sw) { keys[t] = c; keys[l] = a; }
                }
            }
            __syncthreads();
        }
    }

    // ---- Phase 5: gather rows + emit outputs (one warp per output row) ----
    const int wid = tid >> 5;
    for (int j = wid; j < TOPK; j += NTHREADS / 32) {
        unsigned long long key = keys[j];
        unsigned int bits = (unsigned int)(key >> 32);
        int idx = (int)(~((unsigned int)key));
        float val = __uint_as_float(bits);
        float valid = (val > 0.25f) ? val : 0.0f;

        const float* row = batch + (size_t)idx * NDIM;

        if (lane < 4) {
            // xywh -> xyxy: lanes 0,1 = xy - 0.5*wh ; lanes 2,3 = xy + 0.5*wh
            float xy = row[lane & 1];
            float wh = row[2 + (lane & 1)];
            float half = wh * 0.5f;
            float r = (lane < 2) ? (xy - half) : (xy + half);
            boxes_out[((size_t)b * TOPK + j) * 4 + lane] = r;
        }

#pragma unroll
        for (int c = lane; c < NCLS; c += 32) {
            float m = row[5 + c] * valid;
            scores_out[((size_t)b * TOPK + j) * NCLS + c] = (m > 0.25f) ? m : 0.0f;
        }
    }
}

extern "C" void kernel_launch(void* const* d_in, const int* in_sizes, int n_in,
                              void* d_out, int out_size) {
    const float* pred = (const float*)d_in[0];
    int B = in_sizes[0] / (N_ANCH * NDIM);

    float* out    = (float*)d_out;
    float* scores = out;                                  // (B, TOPK, NCLS)
    float* boxes  = out + (size_t)B * TOPK * NCLS;        // (B, TOPK, 4)

    yolo_topk_post_kernel<<<B, NTHREADS>>>(pred, scores, boxes);
}

// round 2
// speedup vs baseline: 1.0917x; 1.0917x over previous
#include <cuda_runtime.h>
#include <stdint.h>

#define N_ANCH   25200
#define NDIM     85
#define NCLS     80
#define TOPK     1000
#define NB_MAX   32
#define HBINS    16384
#define HSHIFT   18
#define CANDMAX  4096
#define SLICES   8
#define SLICE_LEN (N_ANCH / SLICES)   // 3150

__device__ unsigned int       g_hist[NB_MAX][HBINS];
__device__ unsigned long long g_cand[NB_MAX][CANDMAX];
__device__ int                g_cnt[NB_MAX];
__device__ unsigned int       g_thresh[NB_MAX];

// ---------------- K0: zero hist + counters ----------------
__global__ void k0_zero(int B) {
    uint4* p = (uint4*)g_hist;
    int n = B * HBINS / 4;
    for (int i = blockIdx.x * blockDim.x + threadIdx.x; i < n;
         i += gridDim.x * blockDim.x)
        p[i] = make_uint4(0, 0, 0, 0);
    if (blockIdx.x == 0 && threadIdx.x < NB_MAX) g_cnt[threadIdx.x] = 0;
}

// ---------------- K1: histogram of score bit patterns ----------------
// scores in [0,1): positive fp32 -> uint bit order == value order.
__global__ __launch_bounds__(512) void k1_hist(const float* __restrict__ pred) {
    const int b = blockIdx.y, s = blockIdx.x;
    const float* base = pred + (size_t)b * N_ANCH * NDIM;
    const int i0 = s * SLICE_LEN;
    for (int t = threadIdx.x; t < SLICE_LEN; t += 512) {
        unsigned int bits = __float_as_uint(base[(size_t)(i0 + t) * NDIM + 4]);
        atomicAdd(&g_hist[b][bits >> HSHIFT], 1u);
    }
}

// ---------------- K2a: find threshold bin (count >= TOPK) ----------------
__global__ __launch_bounds__(1024) void k2a_thresh() {
    __shared__ unsigned int s_suf[1024];
    const int b = blockIdx.x, tid = threadIdx.x;
    unsigned int loc[HBINS / 1024];              // 16 bins per thread
    unsigned int tot = 0;
#pragma unroll
    for (int i = 0; i < HBINS / 1024; i++) {
        loc[i] = g_hist[b][tid * (HBINS / 1024) + i];
        tot += loc[i];
    }
    s_suf[tid] = tot;
    __syncthreads();
    // Hillis-Steele suffix scan: s_suf[t] = sum over threads >= t
    for (int off = 1; off < 1024; off <<= 1) {
        unsigned int v = (tid + off < 1024) ? s_suf[tid + off] : 0u;
        __syncthreads();
        s_suf[tid] += v;
        __syncthreads();
    }
    unsigned int S = s_suf[tid];  // items in bins >= tid*16
#pragma unroll
    for (int i = 0; i < HBINS / 1024; i++) {
        // bin is the threshold bin iff C(bin) >= K and C(bin+1) < K
        if (S >= TOPK && S - loc[i] < TOPK)
            g_thresh[b] = (unsigned int)(tid * (HBINS / 1024) + i) << HSHIFT;
        S -= loc[i];
    }
}

// ---------------- K2b: compact candidates (bits >= thresh) ----------------
__global__ __launch_bounds__(512) void k2b_compact(const float* __restrict__ pred) {
    const int b = blockIdx.y, s = blockIdx.x;
    const unsigned int thr = g_thresh[b];
    const float* base = pred + (size_t)b * N_ANCH * NDIM;
    const int i0 = s * SLICE_LEN;
    const int lane = threadIdx.x & 31;
    const int iters = (SLICE_LEN + 511) / 512;
    for (int it = 0; it < iters; it++) {
        int t = threadIdx.x + it * 512;
        unsigned int bits = 0;
        bool c = false;
        int idx = i0 + t;
        if (t < SLICE_LEN) {
            bits = __float_as_uint(base[(size_t)idx * NDIM + 4]);
            c = (bits >= thr);
        }
        unsigned int m = __ballot_sync(0xffffffffu, c);
        if (m) {
            int leader = __ffs(m) - 1;
            int basep = 0;
            if (lane == leader) basep = atomicAdd(&g_cnt[b], __popc(m));
            basep = __shfl_sync(0xffffffffu, basep, leader);
            if (c) {
                int pos = basep + __popc(m & ((1u << lane) - 1u));
                if (pos < CANDMAX)
                    g_cand[b][pos] = ((unsigned long long)bits << 32) |
                                     (unsigned int)(~(unsigned int)idx);
            }
        }
    }
}

// ---------------- K3: rank-by-counting + gather + emit ----------------
__global__ __launch_bounds__(256) void k3_emit(const float* __restrict__ pred,
                                               float* __restrict__ scores_out,
                                               float* __restrict__ boxes_out) {
    __shared__ unsigned long long s_keys[CANDMAX];
    __shared__ int s_rank[(CANDMAX + 15) / 16];   // max chunk = 256
    const int b = blockIdx.y, blk = blockIdx.x;   // 16 blocks per batch
    const int tid = threadIdx.x, lane = tid & 31, wid = tid >> 5;

    int cnt = g_cnt[b];
    if (cnt > CANDMAX) cnt = CANDMAX;
    for (int i = tid; i < cnt; i += 256) s_keys[i] = g_cand[b][i];
    __syncthreads();

    const int chunk = (cnt + 15) >> 4;
    const int c0 = blk * chunk;
    const int c1 = min(c0 + chunk, cnt);

    // warp-per-candidate exact rank: #{keys strictly greater}
    for (int c = c0 + wid; c < c1; c += 8) {
        const unsigned long long key = s_keys[c];
        int r = 0;
        for (int j = lane; j < cnt; j += 32) r += (s_keys[j] > key);
        r = __reduce_add_sync(0xffffffffu, r);
        if (lane == 0) s_rank[c - c0] = r;
    }
    __syncthreads();

    const float* batch = pred + (size_t)b * N_ANCH * NDIM;
    for (int c = c0 + wid; c < c1; c += 8) {
        const int r = s_rank[c - c0];
        if (r >= TOPK) continue;
        const unsigned long long key = s_keys[c];
        const unsigned int bits = (unsigned int)(key >> 32);
        const int idx = (int)(~(unsigned int)key);
        const float val = __uint_as_float(bits);
        const float valid = (val > 0.25f) ? val : 0.0f;
        const float* row = batch + (size_t)idx * NDIM;

        if (lane < 4) {
            // xywh -> xyxy
            float xy = row[lane & 1];
            float wh = row[2 + (lane & 1)];
            float half = wh * 0.5f;
            float o = (lane < 2) ? (xy - half) : (xy + half);
            boxes_out[((size_t)b * TOPK + r) * 4 + lane] = o;
        }
#pragma unroll
        for (int cc = lane; cc < NCLS; cc += 32) {
            float m = row[5 + cc] * valid;
            scores_out[((size_t)b * TOPK + r) * NCLS + cc] = (m > 0.25f) ? m : 0.0f;
        }
    }
}

extern "C" void kernel_launch(void* const* d_in, const int* in_sizes, int n_in,
                              void* d_out, int out_size) {
    const float* pred = (const float*)d_in[0];
    const int B = in_sizes[0] / (N_ANCH * NDIM);

    float* scores = (float*)d_out;                          // (B, TOPK, NCLS)
    float* boxes  = scores + (size_t)B * TOPK * NCLS;       // (B, TOPK, 4)

    k0_zero<<<128, 512>>>(B);
    k1_hist<<<dim3(SLICES, B), 512>>>(pred);
    k2a_thresh<<<B, 1024>>>();
    k2b_compact<<<dim3(SLICES, B), 512>>>(pred);
    k3_emit<<<dim3(16, B), 256>>>(pred, scores, boxes);
}

// round 3
// speedup vs baseline: 1.2977x; 1.1886x over previous
#include <cuda_runtime.h>
#include <stdint.h>

#define N_ANCH   25200
#define NDIM     85
#define NCLS     80
#define TOPK     1000
#define NB_MAX   32
#define NBINS    4096
#define BCAP     32
#define CANDMAX  4096
#define BLK_ITEMS 2048
#define NBLK     ((N_ANCH + BLK_ITEMS - 1) / BLK_ITEMS)   // 13

__device__ unsigned int       g_hist[NB_MAX][NBINS];
__device__ unsigned long long g_bucket[NB_MAX][NBINS * BCAP];
__device__ unsigned long long g_cand[NB_MAX][CANDMAX];
__device__ int                g_cnt[NB_MAX];
__device__ int                g_tbin[NB_MAX];
__device__ int                g_resc[NB_MAX];

// ---------------- K0: zero hist + counters ----------------
__global__ void k0_zero(int B) {
    uint4* p = (uint4*)g_hist;
    int n = B * NBINS / 4;
    for (int i = blockIdx.x * blockDim.x + threadIdx.x; i < n;
         i += gridDim.x * blockDim.x)
        p[i] = make_uint4(0, 0, 0, 0);
    if (blockIdx.x == 0 && threadIdx.x < NB_MAX) {
        g_cnt[threadIdx.x]  = 0;
        g_resc[threadIdx.x] = 0;
    }
}

// ---------------- K1: single scan -> hist + bucket scatter ----------------
// scores in [0,1): linear bin is monotone in value; atomicAdd return = slot.
__global__ __launch_bounds__(512) void k1_scan(const float* __restrict__ pred) {
    const int b  = blockIdx.y;
    const int i0 = blockIdx.x * BLK_ITEMS;
    const float* base = pred + (size_t)b * N_ANCH * NDIM;

    float v[4];
    int   idx[4];
#pragma unroll
    for (int s = 0; s < 4; s++) {            // batch the loads (MLP=4)
        idx[s] = i0 + s * 512 + threadIdx.x;
        v[s] = (idx[s] < N_ANCH) ? base[(size_t)idx[s] * NDIM + 4] : -1.0f;
    }
#pragma unroll
    for (int s = 0; s < 4; s++) {
        if (idx[s] >= N_ANCH) continue;
        float f = v[s];
        int bin = (int)(f * (float)NBINS);
        bin = min(max(bin, 0), NBINS - 1);
        unsigned int pos = atomicAdd(&g_hist[b][bin], 1u);
        if (pos < BCAP)
            g_bucket[b][bin * BCAP + pos] =
                ((unsigned long long)__float_as_uint(f) << 32) |
                (unsigned int)(~(unsigned int)idx[s]);
    }
}

// ---------------- K2a: threshold bin + bucket compaction ----------------
__global__ __launch_bounds__(1024) void k2a_select() {
    __shared__ unsigned int s_suf[1024];
    __shared__ int s_tbin;
    __shared__ int s_pos;
    const int b = blockIdx.x, tid = threadIdx.x;

    unsigned int loc[NBINS / 1024];          // 4 bins per thread
    unsigned int tot = 0;
#pragma unroll
    for (int i = 0; i < NBINS / 1024; i++) {
        loc[i] = g_hist[b][tid * (NBINS / 1024) + i];
        tot += loc[i];
    }
    s_suf[tid] = tot;
    if (tid == 0) s_pos = 0;
    __syncthreads();
    for (int off = 1; off < 1024; off <<= 1) {   // suffix scan
        unsigned int t = (tid + off < 1024) ? s_suf[tid + off] : 0u;
        __syncthreads();
        s_suf[tid] += t;
        __syncthreads();
    }
    unsigned int S = s_suf[tid];             // count in bins >= tid*4
#pragma unroll
    for (int i = 0; i < NBINS / 1024; i++) {
        if (S >= TOPK && S - loc[i] < TOPK)  // exactly one bin satisfies this
            s_tbin = tid * (NBINS / 1024) + i;
        S -= loc[i];
    }
    __syncthreads();
    const int tbin = s_tbin;

    // any candidate bin overflowed its bucket?
    bool ovf = false;
    for (int bin = tbin + tid; bin < NBINS; bin += 1024)
        ovf |= (g_hist[b][bin] > BCAP);
    if (__syncthreads_or(ovf)) {             // rare: defer to repair rescan
        if (tid == 0) { g_resc[b] = 1; g_tbin[b] = tbin; g_cnt[b] = 0; }
        return;
    }
    // compact candidate buckets into dense array (order irrelevant)
    for (int bin = tbin + tid; bin < NBINS; bin += 1024) {
        int c = (int)g_hist[b][bin];
        if (!c) continue;
        int p = atomicAdd(&s_pos, c);
        for (int j = 0; j < c; j++)
            if (p + j < CANDMAX)
                g_cand[b][p + j] = g_bucket[b][bin * BCAP + j];
    }
    __syncthreads();
    if (tid == 0) { g_cnt[b] = min(s_pos, CANDMAX); g_tbin[b] = tbin; }
}

// ---------------- K2b: repair rescan (normally a no-op) ----------------
__global__ __launch_bounds__(512) void k2b_repair(const float* __restrict__ pred) {
    const int b = blockIdx.y;
    if (!g_resc[b]) return;
    const int tbin = g_tbin[b];
    const float* base = pred + (size_t)b * N_ANCH * NDIM;
    const int i0 = blockIdx.x * BLK_ITEMS;
#pragma unroll
    for (int s = 0; s < 4; s++) {
        int i = i0 + s * 512 + threadIdx.x;
        if (i >= N_ANCH) continue;
        float f = base[(size_t)i * NDIM + 4];
        int bin = min(max((int)(f * (float)NBINS), 0), NBINS - 1);
        if (bin >= tbin) {
            int p = atomicAdd(&g_cnt[b], 1);
            if (p < CANDMAX)
                g_cand[b][p] = ((unsigned long long)__float_as_uint(f) << 32) |
                               (unsigned int)(~(unsigned int)i);
        }
    }
}

// ---------------- K3: rank-by-counting + gather + emit ----------------
__global__ __launch_bounds__(256) void k3_emit(const float* __restrict__ pred,
                                               float* __restrict__ scores_out,
                                               float* __restrict__ boxes_out) {
    __shared__ unsigned long long s_keys[CANDMAX];
    __shared__ int s_rank[(CANDMAX + 15) / 16];
    const int b = blockIdx.y, blk = blockIdx.x;   // 16 blocks per batch
    const int tid = threadIdx.x, lane = tid & 31, wid = tid >> 5;

    int cnt = g_cnt[b];
    if (cnt > CANDMAX) cnt = CANDMAX;
    for (int i = tid; i < cnt; i += 256) s_keys[i] = g_cand[b][i];
    __syncthreads();

    const int chunk = (cnt + 15) >> 4;
    const int c0 = blk * chunk;
    const int c1 = min(c0 + chunk, cnt);

    for (int c = c0 + wid; c < c1; c += 8) {      // warp-per-candidate rank
        const unsigned long long key = s_keys[c];
        int r = 0;
        for (int j = lane; j < cnt; j += 32) r += (s_keys[j] > key);
        r = __reduce_add_sync(0xffffffffu, r);
        if (lane == 0) s_rank[c - c0] = r;
    }
    __syncthreads();

    const float* batch = pred + (size_t)b * N_ANCH * NDIM;
    for (int c = c0 + wid; c < c1; c += 8) {
        const int r = s_rank[c - c0];
        if (r >= TOPK) continue;
        const unsigned long long key = s_keys[c];
        const int idx = (int)(~(unsigned int)key);
        const float val = __uint_as_float((unsigned int)(key >> 32));
        const float valid = (val > 0.25f) ? val : 0.0f;
        const float* row = batch + (size_t)idx * NDIM;

        if (lane < 4) {                           // xywh -> xyxy
            float xy = row[lane & 1];
            float wh = row[2 + (lane & 1)];
            float half = wh * 0.5f;
            float o = (lane < 2) ? (xy - half) : (xy + half);
            boxes_out[((size_t)b * TOPK + r) * 4 + lane] = o;
        }
#pragma unroll
        for (int cc = lane; cc < NCLS; cc += 32) {
            float m = row[5 + cc] * valid;
            scores_out[((size_t)b * TOPK + r) * NCLS + cc] = (m > 0.25f) ? m : 0.0f;
        }
    }
}

extern "C" void kernel_launch(void* const* d_in, const int* in_sizes, int n_in,
                              void* d_out, int out_size) {
    const float* pred = (const float*)d_in[0];
    const int B = in_sizes[0] / (N_ANCH * NDIM);

    float* scores = (float*)d_out;                       // (B, TOPK, NCLS)
    float* boxes  = scores + (size_t)B * TOPK * NCLS;    // (B, TOPK, 4)

    k0_zero<<<64, 512>>>(B);
    k1_scan<<<dim3(NBLK, B), 512>>>(pred);
    k2a_select<<<B, 1024>>>();
    k2b_repair<<<dim3(NBLK, B), 512>>>(pred);
    k3_emit<<<dim3(16, B), 256>>>(pred, scores, boxes);
}

// round 4
// speedup vs baseline: 1.5462x; 1.1915x over previous
#include <cuda_runtime.h>
#include <stdint.h>

#define N_ANCH   25200
#define NDIM     85
#define NCLS     80
#define TOPK     1000
#define NB_MAX   32
#define NBINS    4096
#define BCAP     16
#define CANDMAX  2048
#define FLOORF   0.9375f           // capture floor; bins span [0.9375, 1)
#define BINSCALE 65536.0f          // 4096 / 0.0625
#define K1_THREADS 256
#define K1_MLP     8
#define BLK_ITEMS  (K1_THREADS * K1_MLP)                 // 2048
#define NBLK       ((N_ANCH + BLK_ITEMS - 1) / BLK_ITEMS) // 13
#define NPT        25              // rescue: ceil(25200/1024)

__device__ unsigned int       g_hist[NB_MAX][NBINS];
__device__ unsigned long long g_bucket[NB_MAX][NBINS * BCAP];
__device__ unsigned long long g_cand[NB_MAX][CANDMAX];
__device__ int                g_cnt[NB_MAX];

// ---------------- K0: zero hist ----------------
__global__ void k0_zero(int B) {
    uint4* p = (uint4*)g_hist;
    int n = B * NBINS / 4;
    for (int i = blockIdx.x * blockDim.x + threadIdx.x; i < n;
         i += gridDim.x * blockDim.x)
        p[i] = make_uint4(0, 0, 0, 0);
}

// ---------------- K1: pure scan; capture only items >= FLOORF ----------------
// scores in [0,1): bin is monotone in value on [FLOORF, 1).
__global__ __launch_bounds__(K1_THREADS) void k1_scan(const float* __restrict__ pred) {
    const int b  = blockIdx.y;
    const int i0 = blockIdx.x * BLK_ITEMS;
    const float* base = pred + (size_t)b * N_ANCH * NDIM;

    float v[K1_MLP];
    int   idx[K1_MLP];
#pragma unroll
    for (int s = 0; s < K1_MLP; s++) {       // batch the loads (MLP=8)
        idx[s] = i0 + s * K1_THREADS + threadIdx.x;
        v[s] = (idx[s] < N_ANCH) ? base[(size_t)idx[s] * NDIM + 4] : 0.0f;
    }
#pragma unroll
    for (int s = 0; s < K1_MLP; s++) {
        float f = v[s];
        if (idx[s] >= N_ANCH || !(f >= FLOORF)) continue;   // 97% exit here
        int bin = (int)((f - FLOORF) * BINSCALE);
        bin = min(max(bin, 0), NBINS - 1);
        unsigned int pos = atomicAdd(&g_hist[b][bin], 1u);
        if (pos < BCAP)
            g_bucket[b][bin * BCAP + pos] =
                ((unsigned long long)__float_as_uint(f) << 32) |
                (unsigned int)(~(unsigned int)idx[s]);
    }
}

// ---------------- K2: threshold bin + compact (+ exact in-kernel rescue) ----------------
__global__ __launch_bounds__(1024) void k2_select(const float* __restrict__ pred) {
    __shared__ unsigned int s_suf[1024];
    __shared__ int s_tbin, s_pos, s_flag;
    __shared__ unsigned int s_hist256[256];
    __shared__ unsigned int s_sel, s_k;

    const int b = blockIdx.x, tid = threadIdx.x, lane = tid & 31;

    unsigned int loc[NBINS / 1024];          // 4 bins per thread
    unsigned int tot = 0;
#pragma unroll
    for (int i = 0; i < NBINS / 1024; i++) {
        loc[i] = g_hist[b][tid * (NBINS / 1024) + i];
        tot += loc[i];
    }
    s_suf[tid] = tot;
    if (tid == 0) { s_pos = 0; s_flag = 0; }
    __syncthreads();
    for (int off = 1; off < 1024; off <<= 1) {   // suffix scan over thread sums
        unsigned int t = (tid + off < 1024) ? s_suf[tid + off] : 0u;
        __syncthreads();
        s_suf[tid] += t;
        __syncthreads();
    }
    const unsigned int total = s_suf[0];     // items >= FLOORF

    if (total >= TOPK) {
        unsigned int S = s_suf[tid];
#pragma unroll
        for (int i = 0; i < NBINS / 1024; i++) {
            if (S >= TOPK && S - loc[i] < TOPK)      // unique crossing bin
                s_tbin = tid * (NBINS / 1024) + i;
            S -= loc[i];
        }
    } else if (tid == 0) s_flag = 1;
    __syncthreads();

    if (!s_flag) {
        // overflow check among candidate bins
        bool ovf = false;
        for (int bin = s_tbin + tid; bin < NBINS; bin += 1024)
            ovf |= (g_hist[b][bin] > BCAP);
        if (__syncthreads_or(ovf)) { if (tid == 0) s_flag = 1; }
        __syncthreads();
    }

    if (!s_flag) {
        // fast path: compact candidate buckets (order irrelevant)
        for (int bin = s_tbin + tid; bin < NBINS; bin += 1024) {
            int c = (int)g_hist[b][bin];
            if (!c) continue;
            int p = atomicAdd(&s_pos, c);
            for (int j = 0; j < c; j++)
                if (p + j < CANDMAX)
                    g_cand[b][p + j] = g_bucket[b][bin * BCAP + j];
        }
        __syncthreads();
        if (tid == 0) g_cnt[b] = min(s_pos, CANDMAX);
        return;
    }

    // ---------- rescue: exact register-resident radix select (never on this data) ----------
    const float* base = pred + (size_t)b * N_ANCH * NDIM;
    unsigned int rv[NPT];
#pragma unroll
    for (int s = 0; s < NPT; s++) {
        int i = s * 1024 + tid;
        rv[s] = (i < N_ANCH) ? __float_as_uint(base[(size_t)i * NDIM + 4]) : 0u;
    }
    if (tid == 0) s_k = TOPK;
    __syncthreads();
    unsigned int prefix = 0, prefmask = 0;
    for (int pass = 0; pass < 4; pass++) {
        const int shift = 24 - 8 * pass;
        if (tid < 256) s_hist256[tid] = 0;
        __syncthreads();
#pragma unroll
        for (int s = 0; s < NPT; s++) {
            int i = s * 1024 + tid;
            bool ok = (i < N_ANCH) && ((rv[s] & prefmask) == prefix);
            unsigned int digit = ok ? ((rv[s] >> shift) & 255u) : 0xffffffffu;
            unsigned int m = __match_any_sync(0xffffffffu, digit);
            if (ok && lane == (__ffs(m) - 1))
                atomicAdd(&s_hist256[digit], (unsigned int)__popc(m));
        }
        __syncthreads();
        unsigned int kcur = s_k;
        __syncthreads();
        for (int off = 1; off < 256; off <<= 1) {    // suffix scan
            unsigned int t = 0;
            if (tid < 256 && tid + off < 256) t = s_hist256[tid + off];
            __syncthreads();
            if (tid < 256) s_hist256[tid] += t;
            __syncthreads();
        }
        if (tid < 256) {
            unsigned int ge = s_hist256[tid];
            unsigned int gt = (tid == 255) ? 0u : s_hist256[tid + 1];
            if (ge >= kcur && gt < kcur) { s_sel = (unsigned int)tid; s_k = kcur - gt; }
        }
        __syncthreads();
        prefix   |= s_sel << shift;
        prefmask |= 255u << shift;
        __syncthreads();
    }
#pragma unroll
    for (int s = 0; s < NPT; s++) {
        int i = s * 1024 + tid;
        if (i < N_ANCH && rv[s] >= prefix) {
            int p = atomicAdd(&s_pos, 1);
            if (p < CANDMAX)
                g_cand[b][p] = ((unsigned long long)rv[s] << 32) |
                               (unsigned int)(~(unsigned int)i);
        }
    }
    __syncthreads();
    if (tid == 0) g_cnt[b] = min(s_pos, CANDMAX);
}

// ---------------- K3: rank-by-counting + gather + emit ----------------
__global__ __launch_bounds__(256) void k3_emit(const float* __restrict__ pred,
                                               float* __restrict__ scores_out,
                                               float* __restrict__ boxes_out) {
    __shared__ unsigned long long s_keys[CANDMAX];
    __shared__ int s_rank[(CANDMAX + 15) / 16];
    const int b = blockIdx.y, blk = blockIdx.x;   // 16 blocks per batch
    const int tid = threadIdx.x, lane = tid & 31, wid = tid >> 5;

    int cnt = g_cnt[b];
    if (cnt > CANDMAX) cnt = CANDMAX;
    for (int i = tid; i < cnt; i += 256) s_keys[i] = g_cand[b][i];
    __syncthreads();

    const int chunk = (cnt + 15) >> 4;
    const int c0 = blk * chunk;
    const int c1 = min(c0 + chunk, cnt);

    for (int c = c0 + wid; c < c1; c += 8) {      // warp-per-candidate exact rank
        const unsigned long long key = s_keys[c];
        int r = 0;
        for (int j = lane; j < cnt; j += 32) r += (s_keys[j] > key);
        r = __reduce_add_sync(0xffffffffu, r);
        if (lane == 0) s_rank[c - c0] = r;
    }
    __syncthreads();

    const float* batch = pred + (size_t)b * N_ANCH * NDIM;
    for (int c = c0 + wid; c < c1; c += 8) {
        const int r = s_rank[c - c0];
        if (r >= TOPK) continue;
        const unsigned long long key = s_keys[c];
        const int idx = (int)(~(unsigned int)key);
        const float val = __uint_as_float((unsigned int)(key >> 32));
        const float valid = (val > 0.25f) ? val : 0.0f;
        const float* row = batch + (size_t)idx * NDIM;

        if (lane < 4) {                           // xywh -> xyxy
            float xy = row[lane & 1];
            float wh = row[2 + (lane & 1)];
            float half = wh * 0.5f;
            float o = (lane < 2) ? (xy - half) : (xy + half);
            boxes_out[((size_t)b * TOPK + r) * 4 + lane] = o;
        }
#pragma unroll
        for (int cc = lane; cc < NCLS; cc += 32) {
            float m = row[5 + cc] * valid;
            scores_out[((size_t)b * TOPK + r) * NCLS + cc] = (m > 0.25f) ? m : 0.0f;
        }
    }
}

extern "C" void kernel_launch(void* const* d_in, const int* in_sizes, int n_in,
                              void* d_out, int out_size) {
    const float* pred = (const float*)d_in[0];
    const int B = in_sizes[0] / (N_ANCH * NDIM);

    float* scores = (float*)d_out;                       // (B, TOPK, NCLS)
    float* boxes  = scores + (size_t)B * TOPK * NCLS;    // (B, TOPK, 4)

    k0_zero<<<64, 256>>>(B);
    k1_scan<<<dim3(NBLK, B), K1_THREADS>>>(pred);
    k2_select<<<B, 1024>>>(pred);
    k3_emit<<<dim3(16, B), 256>>>(pred, scores, boxes);
}

// round 5
// speedup vs baseline: 1.8739x; 1.2119x over previous
#include <cuda_runtime.h>
#include <stdint.h>

#define N_ANCH   25200
#define NDIM     85
#define NCLS     80
#define TOPK     1000
#define NB_MAX   32
#define NBINS    4096
#define BCAP     16
#define CAND     2048              // rescue sort size (power of 2)
#define FLOORF   0.9375f           // capture floor; bins span [0.9375, 1)
#define BINSCALE 65536.0f          // 4096 / 0.0625
#define K1_THREADS 256
#define K1_MLP     8
#define BLK_ITEMS  (K1_THREADS * K1_MLP)                  // 2048
#define NBLK       ((N_ANCH + BLK_ITEMS - 1) / BLK_ITEMS) // 13
#define NPT        25              // rescue: ceil(25200/1024)

__device__ unsigned int       g_hist[NB_MAX][NBINS];      // zero-init; K2 re-zeroes
__device__ unsigned long long g_bucket[NB_MAX][NBINS * BCAP];
__device__ unsigned long long g_cand[NB_MAX][TOPK];       // rank-ordered keys

// ---------------- K1: pure scan; capture only items >= FLOORF ----------------
// scores in [0,1): linear bin is monotone in value on [FLOORF, 1).
__global__ __launch_bounds__(K1_THREADS) void k1_scan(const float* __restrict__ pred) {
    const int b  = blockIdx.y;
    const int i0 = blockIdx.x * BLK_ITEMS;
    const float* base = pred + (size_t)b * N_ANCH * NDIM;

    float v[K1_MLP];
    int   idx[K1_MLP];
#pragma unroll
    for (int s = 0; s < K1_MLP; s++) {       // batch the loads (MLP=8)
        idx[s] = i0 + s * K1_THREADS + threadIdx.x;
        v[s] = (idx[s] < N_ANCH) ? base[(size_t)idx[s] * NDIM + 4] : 0.0f;
    }
#pragma unroll
    for (int s = 0; s < K1_MLP; s++) {
        float f = v[s];
        if (idx[s] >= N_ANCH || !(f >= FLOORF)) continue;   // ~97% exit here
        int bin = (int)((f - FLOORF) * BINSCALE);
        bin = min(max(bin, 0), NBINS - 1);
        unsigned int pos = atomicAdd(&g_hist[b][bin], 1u);
        if (pos < BCAP)
            g_bucket[b][bin * BCAP + pos] =
                ((unsigned long long)__float_as_uint(f) << 32) |
                (unsigned int)(~(unsigned int)idx[s]);
    }
}

// ---------------- K2: exact global rank per candidate -> g_cand[rank] ----------------
__global__ __launch_bounds__(1024) void k2_select(const float* __restrict__ pred) {
    __shared__ unsigned int s_suf[1024];
    __shared__ int s_tbin, s_pos, s_flag;
    __shared__ unsigned int s_hist256[256];
    __shared__ unsigned int s_sel, s_k;
    __shared__ unsigned long long s_keys[CAND];   // rescue only

    const int b = blockIdx.x, tid = threadIdx.x, lane = tid & 31;

    // load my 4 contiguous bins (vectorized), then immediately re-zero them
    uint4 h4 = ((uint4*)g_hist[b])[tid];
    ((uint4*)g_hist[b])[tid] = make_uint4(0, 0, 0, 0);
    unsigned int loc[4] = {h4.x, h4.y, h4.z, h4.w};
    unsigned int tot = loc[0] + loc[1] + loc[2] + loc[3];

    s_suf[tid] = tot;
    if (tid == 0) { s_pos = 0; s_flag = 0; }
    __syncthreads();
    for (int off = 1; off < 1024; off <<= 1) {   // suffix scan over thread sums
        unsigned int t = (tid + off < 1024) ? s_suf[tid + off] : 0u;
        __syncthreads();
        s_suf[tid] += t;
        __syncthreads();
    }
    const unsigned int total = s_suf[0];     // items >= FLOORF

    if (total >= TOPK) {
        unsigned int S = s_suf[tid];
#pragma unroll
        for (int i = 0; i < 4; i++) {
            if (S >= TOPK && S - loc[i] < TOPK)      // unique crossing bin
                s_tbin = tid * 4 + i;
            S -= loc[i];
        }
    } else if (tid == 0) s_flag = 1;
    __syncthreads();
    const int tbin = s_tbin;

    // overflow check on owned candidate bins
    bool ovf = false;
#pragma unroll
    for (int i = 0; i < 4; i++)
        ovf |= (tid * 4 + i >= tbin) && (loc[i] > BCAP);
    if (__syncthreads_or(ovf)) { if (tid == 0) s_flag = 1; }
    __syncthreads();

    if (!s_flag) {
        // gt[i] = #items in bins strictly above bin (tid*4+i)
        unsigned int acc = (tid < 1023) ? s_suf[tid + 1] : 0u;
        unsigned int gt[4];
#pragma unroll
        for (int i = 3; i >= 0; i--) { gt[i] = acc; acc += loc[i]; }

#pragma unroll
        for (int i = 0; i < 4; i++) {
            const int bin = tid * 4 + i;
            const int c = (int)loc[i];
            if (bin < tbin || c == 0 || gt[i] >= TOPK) continue;
            unsigned long long kk[BCAP];
            for (int j = 0; j < c; j++) kk[j] = g_bucket[b][bin * BCAP + j];
            for (int j = 0; j < c; j++) {        // in-bin rank: (value desc, idx asc)
                int r = (int)gt[i];
                for (int m = 0; m < c; m++) r += (kk[m] > kk[j]);
                if (r < TOPK) g_cand[b][r] = kk[j];
            }
        }
        return;
    }

    // ---------- rescue: exact radix select + bitonic sort (never on this data) ----------
    const float* base = pred + (size_t)b * N_ANCH * NDIM;
    unsigned int rv[NPT];
#pragma unroll
    for (int s = 0; s < NPT; s++) {
        int i = s * 1024 + tid;
        rv[s] = (i < N_ANCH) ? __float_as_uint(base[(size_t)i * NDIM + 4]) : 0u;
    }
    if (tid == 0) s_k = TOPK;
    __syncthreads();
    unsigned int prefix = 0, prefmask = 0;
    for (int pass = 0; pass < 4; pass++) {
        const int shift = 24 - 8 * pass;
        if (tid < 256) s_hist256[tid] = 0;
        __syncthreads();
#pragma unroll
        for (int s = 0; s < NPT; s++) {
            int i = s * 1024 + tid;
            bool ok = (i < N_ANCH) && ((rv[s] & prefmask) == prefix);
            unsigned int digit = ok ? ((rv[s] >> shift) & 255u) : 0xffffffffu;
            unsigned int m = __match_any_sync(0xffffffffu, digit);
            if (ok && lane == (__ffs(m) - 1))
                atomicAdd(&s_hist256[digit], (unsigned int)__popc(m));
        }
        __syncthreads();
        unsigned int kcur = s_k;
        __syncthreads();
        for (int off = 1; off < 256; off <<= 1) {
            unsigned int t = 0;
            if (tid < 256 && tid + off < 256) t = s_hist256[tid + off];
            __syncthreads();
            if (tid < 256) s_hist256[tid] += t;
            __syncthreads();
        }
        if (tid < 256) {
            unsigned int ge = s_hist256[tid];
            unsigned int gtv = (tid == 255) ? 0u : s_hist256[tid + 1];
            if (ge >= kcur && gtv < kcur) { s_sel = (unsigned int)tid; s_k = kcur - gtv; }
        }
        __syncthreads();
        prefix   |= s_sel << shift;
        prefmask |= 255u << shift;
        __syncthreads();
    }
#pragma unroll
    for (int s = 0; s < NPT; s++) {
        int i = s * 1024 + tid;
        if (i < N_ANCH && rv[s] >= prefix) {
            int p = atomicAdd(&s_pos, 1);
            if (p < CAND)
                s_keys[p] = ((unsigned long long)rv[s] << 32) |
                            (unsigned int)(~(unsigned int)i);
        }
    }
    __syncthreads();
    int cnt = min(s_pos, CAND);
    for (int i = tid; i < CAND; i += 1024)
        if (i >= cnt) s_keys[i] = 0ull;          // padding sorts last
    __syncthreads();
    for (int ksz = 2; ksz <= CAND; ksz <<= 1) {  // bitonic sort, descending
        for (int j = ksz >> 1; j > 0; j >>= 1) {
            for (int t = tid; t < CAND; t += 1024) {
                int l = t ^ j;
                if (l > t) {
                    unsigned long long a = s_keys[t], c2 = s_keys[l];
                    bool sw = ((t & ksz) == 0) ? (a < c2) : (a > c2);
                    if (sw) { s_keys[t] = c2; s_keys[l] = a; }
                }
            }
            __syncthreads();
        }
    }
    if (tid < TOPK) g_cand[b][tid] = s_keys[tid];
    if (tid + 1024 < TOPK) g_cand[b][tid + 1024] = s_keys[tid + 1024];
}

// ---------------- K3: pure gather + emit (one warp per output row) ----------------
__global__ __launch_bounds__(256) void k3_emit(const float* __restrict__ pred,
                                               float* __restrict__ scores_out,
                                               float* __restrict__ boxes_out) {
    const int b = blockIdx.y;
    const int lane = threadIdx.x & 31;
    const int r = blockIdx.x * 8 + (threadIdx.x >> 5);   // 125*8 = 1000 rows
    if (r >= TOPK) return;

    const unsigned long long key = g_cand[b][r];
    const int idx = (int)(~(unsigned int)key);
    const float val = __uint_as_float((unsigned int)(key >> 32));
    const float valid = (val > 0.25f) ? val : 0.0f;
    const float* row = pred + (size_t)b * N_ANCH * NDIM + (size_t)idx * NDIM;

    if (lane < 4) {                              // xywh -> xyxy
        float xy = row[lane & 1];
        float wh = row[2 + (lane & 1)];
        float half = wh * 0.5f;
        float o = (lane < 2) ? (xy - half) : (xy + half);
        boxes_out[((size_t)b * TOPK + r) * 4 + lane] = o;
    }
#pragma unroll
    for (int c = lane; c < NCLS; c += 32) {
        float m = row[5 + c] * valid;
        scores_out[((size_t)b * TOPK + r) * NCLS + c] = (m > 0.25f) ? m : 0.0f;
    }
}

extern "C" void kernel_launch(void* const* d_in, const int* in_sizes, int n_in,
                              void* d_out, int out_size) {
    const float* pred = (const float*)d_in[0];
    const int B = in_sizes[0] / (N_ANCH * NDIM);

    float* scores = (float*)d_out;                       // (B, TOPK, NCLS)
    float* boxes  = scores + (size_t)B * TOPK * NCLS;    // (B, TOPK, 4)

    k1_scan<<<dim3(NBLK, B), K1_THREADS>>>(pred);
    k2_select<<<B, 1024>>>(pred);
    k3_emit<<<dim3((TOPK + 7) / 8, B), 256>>>(pred, scores, boxes);
}

// round 6
// speedup vs baseline: 2.0381x; 1.0877x over previous
#include <cuda_runtime.h>
#include <stdint.h>

#define N_ANCH   25200
#define NDIM     85
#define NCLS     80
#define TOPK     1000
#define NB_MAX   32
#define NBINS    4096
#define BCAP     16
#define CAND     2048              // rescue sort size (power of 2)
#define FLOORF   0.9375f           // capture floor; bins span [0.9375, 1)
#define BINSCALE 65536.0f          // 4096 / 0.0625
#define K1_THREADS 256
#define K1_MLP     2
#define BLK_ITEMS  (K1_THREADS * K1_MLP)                  // 512
#define NBLK       ((N_ANCH + BLK_ITEMS - 1) / BLK_ITEMS) // 50
#define NPT        25              // rescue: ceil(25200/1024)

__device__ unsigned int       g_hist[NB_MAX][NBINS];      // zero-init; K2 re-zeroes
__device__ unsigned long long g_bucket[NB_MAX][NBINS * BCAP];
__device__ unsigned long long g_cand[NB_MAX][TOPK];       // rank-ordered keys

// ---------------- K1: pure scan; capture only items >= FLOORF ----------------
// scores in [0,1): linear bin is monotone in value on [FLOORF, 1).
// __ldcg: L2-only load -> fetch 32B sector, not the 128B L1 line (4x less DRAM).
__global__ __launch_bounds__(K1_THREADS) void k1_scan(const float* __restrict__ pred) {
    const int b  = blockIdx.y;
    const int i0 = blockIdx.x * BLK_ITEMS;
    const float* base = pred + (size_t)b * N_ANCH * NDIM;

    float v[K1_MLP];
    int   idx[K1_MLP];
#pragma unroll
    for (int s = 0; s < K1_MLP; s++) {       // batch the loads
        idx[s] = i0 + s * K1_THREADS + threadIdx.x;
        v[s] = (idx[s] < N_ANCH) ? __ldcg(base + (size_t)idx[s] * NDIM + 4) : 0.0f;
    }
#pragma unroll
    for (int s = 0; s < K1_MLP; s++) {
        float f = v[s];
        if (idx[s] >= N_ANCH || !(f >= FLOORF)) continue;   // ~97% exit here
        int bin = (int)((f - FLOORF) * BINSCALE);
        bin = min(max(bin, 0), NBINS - 1);
        unsigned int pos = atomicAdd(&g_hist[b][bin], 1u);
        if (pos < BCAP)
            g_bucket[b][bin * BCAP + pos] =
                ((unsigned long long)__float_as_uint(f) << 32) |
                (unsigned int)(~(unsigned int)idx[s]);
    }
}

// ---------------- K2: exact global rank per candidate -> g_cand[rank] ----------------
__global__ __launch_bounds__(1024) void k2_select(const float* __restrict__ pred) {
    __shared__ unsigned int s_suf[1024];
    __shared__ int s_tbin, s_pos, s_flag;
    __shared__ unsigned int s_hist256[256];
    __shared__ unsigned int s_sel, s_k;
    __shared__ unsigned long long s_keys[CAND];   // rescue only

    const int b = blockIdx.x, tid = threadIdx.x, lane = tid & 31;

    // load my 4 contiguous bins (vectorized), then immediately re-zero them
    uint4 h4 = ((uint4*)g_hist[b])[tid];
    ((uint4*)g_hist[b])[tid] = make_uint4(0, 0, 0, 0);
    unsigned int loc[4] = {h4.x, h4.y, h4.z, h4.w};
    unsigned int tot = loc[0] + loc[1] + loc[2] + loc[3];

    s_suf[tid] = tot;
    if (tid == 0) { s_pos = 0; s_flag = 0; }
    __syncthreads();
    for (int off = 1; off < 1024; off <<= 1) {   // suffix scan over thread sums
        unsigned int t = (tid + off < 1024) ? s_suf[tid + off] : 0u;
        __syncthreads();
        s_suf[tid] += t;
        __syncthreads();
    }
    const unsigned int total = s_suf[0];     // items >= FLOORF

    if (total >= TOPK) {
        unsigned int S = s_suf[tid];
#pragma unroll
        for (int i = 0; i < 4; i++) {
            if (S >= TOPK && S - loc[i] < TOPK)      // unique crossing bin
                s_tbin = tid * 4 + i;
            S -= loc[i];
        }
    } else if (tid == 0) s_flag = 1;
    __syncthreads();
    const int tbin = s_tbin;

    // overflow check on owned candidate bins
    bool ovf = false;
#pragma unroll
    for (int i = 0; i < 4; i++)
        ovf |= (tid * 4 + i >= tbin) && (loc[i] > BCAP);
    if (__syncthreads_or(ovf)) { if (tid == 0) s_flag = 1; }
    __syncthreads();

    if (!s_flag) {
        // gt[i] = #items in bins strictly above bin (tid*4+i)
        unsigned int acc = (tid < 1023) ? s_suf[tid + 1] : 0u;
        unsigned int gt[4];
#pragma unroll
        for (int i = 3; i >= 0; i--) { gt[i] = acc; acc += loc[i]; }

#pragma unroll
        for (int i = 0; i < 4; i++) {
            const int bin = tid * 4 + i;
            const int c = (int)loc[i];
            if (bin < tbin || c == 0 || gt[i] >= TOPK) continue;
            unsigned long long kk[BCAP];
            for (int j = 0; j < c; j++) kk[j] = g_bucket[b][bin * BCAP + j];
            for (int j = 0; j < c; j++) {        // in-bin rank: (value desc, idx asc)
                int r = (int)gt[i];
                for (int m = 0; m < c; m++) r += (kk[m] > kk[j]);
                if (r < TOPK) g_cand[b][r] = kk[j];
            }
        }
        return;
    }

    // ---------- rescue: exact radix select + bitonic sort (never on this data) ----------
    const float* base = pred + (size_t)b * N_ANCH * NDIM;
    unsigned int rv[NPT];
#pragma unroll
    for (int s = 0; s < NPT; s++) {
        int i = s * 1024 + tid;
        rv[s] = (i < N_ANCH)
              ? __float_as_uint(__ldcg(base + (size_t)i * NDIM + 4)) : 0u;
    }
    if (tid == 0) s_k = TOPK;
    __syncthreads();
    unsigned int prefix = 0, prefmask = 0;
    for (int pass = 0; pass < 4; pass++) {
        const int shift = 24 - 8 * pass;
        if (tid < 256) s_hist256[tid] = 0;
        __syncthreads();
#pragma unroll
        for (int s = 0; s < NPT; s++) {
            int i = s * 1024 + tid;
            bool ok = (i < N_ANCH) && ((rv[s] & prefmask) == prefix);
            unsigned int digit = ok ? ((rv[s] >> shift) & 255u) : 0xffffffffu;
            unsigned int m = __match_any_sync(0xffffffffu, digit);
            if (ok && lane == (__ffs(m) - 1))
                atomicAdd(&s_hist256[digit], (unsigned int)__popc(m));
        }
        __syncthreads();
        unsigned int kcur = s_k;
        __syncthreads();
        for (int off = 1; off < 256; off <<= 1) {
            unsigned int t = 0;
            if (tid < 256 && tid + off < 256) t = s_hist256[tid + off];
            __syncthreads();
            if (tid < 256) s_hist256[tid] += t;
            __syncthreads();
        }
        if (tid < 256) {
            unsigned int ge = s_hist256[tid];
            unsigned int gtv = (tid == 255) ? 0u : s_hist256[tid + 1];
            if (ge >= kcur && gtv < kcur) { s_sel = (unsigned int)tid; s_k = kcur - gtv; }
        }
        __syncthreads();
        prefix   |= s_sel << shift;
        prefmask |= 255u << shift;
        __syncthreads();
    }
#pragma unroll
    for (int s = 0; s < NPT; s++) {
        int i = s * 1024 + tid;
        if (i < N_ANCH && rv[s] >= prefix) {
            int p = atomicAdd(&s_pos, 1);
            if (p < CAND)
                s_keys[p] = ((unsigned long long)rv[s] << 32) |
                            (unsigned int)(~(unsigned int)i);
        }
    }
    __syncthreads();
    int cnt = min(s_pos, CAND);
    for (int i = tid; i < CAND; i += 1024)
        if (i >= cnt) s_keys[i] = 0ull;          // padding sorts last
    __syncthreads();
    for (int ksz = 2; ksz <= CAND; ksz <<= 1) {  // bitonic sort, descending
        for (int j = ksz >> 1; j > 0; j >>= 1) {
            for (int t = tid; t < CAND; t += 1024) {
                int l = t ^ j;
                if (l > t) {
                    unsigned long long a = s_keys[t], c2 = s_keys[l];
                    bool sw = ((t & ksz) == 0) ? (a < c2) : (a > c2);
                    if (sw) { s_keys[t] = c2; s_keys[l] = a; }
                }
            }
            __syncthreads();
        }
    }
    if (tid < TOPK) g_cand[b][tid] = s_keys[tid];
    if (tid + 1024 < TOPK) g_cand[b][tid + 1024] = s_keys[tid + 1024];
}

// ---------------- K3: pure gather + emit (one warp per output row) ----------------
__global__ __launch_bounds__(256) void k3_emit(const float* __restrict__ pred,
                                               float* __restrict__ scores_out,
                                               float* __restrict__ boxes_out) {
    const int b = blockIdx.y;
    const int lane = threadIdx.x & 31;
    const int r = blockIdx.x * 8 + (threadIdx.x >> 5);   // 125*8 = 1000 rows
    if (r >= TOPK) return;

    const unsigned long long key = g_cand[b][r];
    const int idx = (int)(~(unsigned int)key);
    const float val = __uint_as_float((unsigned int)(key >> 32));
    const float valid = (val > 0.25f) ? val : 0.0f;
    const float* row = pred + (size_t)b * N_ANCH * NDIM + (size_t)idx * NDIM;

    if (lane < 4) {                              // xywh -> xyxy
        float xy = row[lane & 1];
        float wh = row[2 + (lane & 1)];
        float half = wh * 0.5f;
        float o = (lane < 2) ? (xy - half) : (xy + half);
        boxes_out[((size_t)b * TOPK + r) * 4 + lane] = o;
    }
#pragma unroll
    for (int c = lane; c < NCLS; c += 32) {
        float m = row[5 + c] * valid;
        scores_out[((size_t)b * TOPK + r) * NCLS + c] = (m > 0.25f) ? m : 0.0f;
    }
}

extern "C" void kernel_launch(void* const* d_in, const int* in_sizes, int n_in,
                              void* d_out, int out_size) {
    const float* pred = (const float*)d_in[0];
    const int B = in_sizes[0] / (N_ANCH * NDIM);

    float* scores = (float*)d_out;                       // (B, TOPK, NCLS)
    float* boxes  = scores + (size_t)B * TOPK * NCLS;    // (B, TOPK, 4)

    k1_scan<<<dim3(NBLK, B), K1_THREADS>>>(pred);
    k2_select<<<B, 1024>>>(pred);
    k3_emit<<<dim3((TOPK + 7) / 8, B), 256>>>(pred, scores, boxes);
}